// round 6
// baseline (speedup 1.0000x reference)
#include <cuda_runtime.h>
#include <cstdint>

// DenseGridNet: trilevel bilinear grid features + MLP 13->64->64->3.
// Persistent-CTA GEMM tiling: 128 points/tile, 128 threads, per-thread tile
// 4 outs x 16 points, point-pairs packed via fma.rn.f32x2 (exact fp32).
// Bank-conflict-mitigated activation layout (RS=160 + per-row 16B swizzle).

#define HID 64
#define EMB 13
#define TILE 128
#define THREADS 128
#define RS 160          // activation row stride in floats (multiple of 32 words)
#define BLOCKS 444      // 148 SMs x 3 CTAs

typedef unsigned long long u64;

__device__ __forceinline__ u64 pack2(float a) {
    u64 r;
    asm("mov.b64 %0, {%1, %1};" : "=l"(r) : "f"(a));
    return r;
}
__device__ __forceinline__ u64 fma2(u64 a, u64 b, u64 c) {
    u64 d;
    asm("fma.rn.f32x2 %0, %1, %2, %3;" : "=l"(d) : "l"(a), "l"(b), "l"(c));
    return d;
}
__device__ __forceinline__ void unpack2(u64 p, float& lo, float& hi) {
    asm("mov.b64 {%0, %1}, %2;" : "=f"(lo), "=f"(hi) : "l"(p));
}
// Row r of an activation matrix starts at r*RS + ((r>>2)&7)*4 floats.
// RS % 32 == 0, so bank-start depends only on the swizzle term -> the 16
// float4 epilogue stores from lanes to=0..15 (rows 4*to+o) hit a bank
// permutation over to&7 (2-way residual from to vs to+8).
__device__ __forceinline__ int rowoff(int r) {
    return r * RS + (((r >> 2) & 7) << 2);
}

struct __align__(16) Smem {
    float w1[EMB * HID];
    float b1[HID];
    float w2[HID * HID];
    float b2[HID];
    float w3[HID * 4];    // 64x3 padded to 64x4 (col 3 = 0)
    float b3[4];
    float xs[3 * TILE];
    float A0[EMB * RS];
    float A1[HID * RS];
};

__device__ __forceinline__ float4 bilerp_level(const float4* __restrict__ tab,
                                               int res, float u, float v) {
    float sx = u * (float)res;
    float sy = v * (float)res;
    int x0 = (int)sx;            // truncation; matches astype(int32) for non-neg
    int y0 = (int)sy;
    float wx = sx - (float)x0;
    float wy = sy - (float)y0;
    int x1 = min(x0 + 1, res);
    int y1 = min(y0 + 1, res);
    // Reference indexes with row stride == res (not res+1). Replicate exactly.
    int r0 = y0 * res;
    int r1 = y1 * res;
    float4 v00 = tab[r0 + x0];
    float4 v10 = tab[r0 + x1];
    float4 v01 = tab[r1 + x0];
    float4 v11 = tab[r1 + x1];
    float omwx = 1.0f - wx;
    float omwy = 1.0f - wy;
    float4 o;
    float t, c;
    t = v00.x * omwx + v10.x * wx; c = v01.x * omwx + v11.x * wx; o.x = t * omwy + c * wy;
    t = v00.y * omwx + v10.y * wx; c = v01.y * omwx + v11.y * wx; o.y = t * omwy + c * wy;
    t = v00.z * omwx + v10.z * wx; c = v01.z * omwx + v11.z * wx; o.z = t * omwy + c * wy;
    t = v00.w * omwx + v10.w * wx; c = v01.w * omwx + v11.w * wx; o.w = t * omwy + c * wy;
    return o;
}

__global__ __launch_bounds__(THREADS, 3)
void densegrid_kernel(const float* __restrict__ x,
                      const float4* __restrict__ emb0,
                      const float4* __restrict__ emb1,
                      const float4* __restrict__ emb2,
                      const float* __restrict__ w1, const float* __restrict__ b1,
                      const float* __restrict__ w2, const float* __restrict__ b2,
                      const float* __restrict__ w3, const float* __restrict__ b3,
                      float* __restrict__ out, int n) {
    extern __shared__ char smem_raw[];
    Smem& s = *reinterpret_cast<Smem*>(smem_raw);

    const int tid = threadIdx.x;

    // ---- one-time weight staging (persistent CTA) ----
    for (int t = tid; t < EMB * HID; t += THREADS) s.w1[t] = w1[t];
    for (int t = tid; t < HID; t += THREADS) s.b1[t] = b1[t];
    for (int t = tid; t < HID * HID; t += THREADS) s.w2[t] = w2[t];
    for (int t = tid; t < HID; t += THREADS) s.b2[t] = b2[t];
    for (int t = tid; t < HID * 4; t += THREADS) {
        int r = t >> 2, c = t & 3;
        s.w3[t] = (c < 3) ? w3[r * 3 + c] : 0.0f;
    }
    if (tid < 4) s.b3[tid] = (tid < 3) ? b3[tid] : 0.0f;

    const int to = tid & 15;   // output quad: outs [4*to .. 4*to+3]
    const int tp = tid >> 4;   // point group: pts [16*tp .. 16*tp+15]
    const int ntiles = (n + TILE - 1) / TILE;

    for (int tile = blockIdx.x; tile < ntiles; tile += gridDim.x) {
        const int base = tile * TILE;

        // ---- stage x coalesced ----
        #pragma unroll
        for (int k = 0; k < 3; k++) {
            int t = tid + k * THREADS;
            int gi = base * 3 + t;
            s.xs[t] = (gi < n * 3) ? x[gi] : 0.0f;
        }
        __syncthreads();

        // ---- phase 0: gather features, one point per thread ----
        {
            float idf = s.xs[3 * tid + 0];
            float u   = s.xs[3 * tid + 1];
            float v   = s.xs[3 * tid + 2];
            float4 f0 = bilerp_level(emb0, 512, u, v);
            float4 f1 = bilerp_level(emb1, 264, u, v);
            float4 f2 = bilerp_level(emb2, 16,  u, v);
            s.A0[rowoff(0)  + tid] = idf;
            s.A0[rowoff(1)  + tid] = f0.x; s.A0[rowoff(2)  + tid] = f0.y;
            s.A0[rowoff(3)  + tid] = f0.z; s.A0[rowoff(4)  + tid] = f0.w;
            s.A0[rowoff(5)  + tid] = f1.x; s.A0[rowoff(6)  + tid] = f1.y;
            s.A0[rowoff(7)  + tid] = f1.z; s.A0[rowoff(8)  + tid] = f1.w;
            s.A0[rowoff(9)  + tid] = f2.x; s.A0[rowoff(10) + tid] = f2.y;
            s.A0[rowoff(11) + tid] = f2.z; s.A0[rowoff(12) + tid] = f2.w;
        }
        __syncthreads();

        // ---- phase 1: 13 -> 64 + relu ----
        {
            u64 acc[4][8];
            #pragma unroll
            for (int o = 0; o < 4; o++) {
                u64 bb = pack2(s.b1[4 * to + o]);
                #pragma unroll
                for (int pp = 0; pp < 8; pp++) acc[o][pp] = bb;
            }
            #pragma unroll
            for (int i = 0; i < EMB; i++) {
                float4 w = *(const float4*)&s.w1[i * HID + 4 * to];
                u64 wp0 = pack2(w.x), wp1 = pack2(w.y), wp2 = pack2(w.z), wp3 = pack2(w.w);
                const ulonglong2* av = (const ulonglong2*)&s.A0[rowoff(i) + 16 * tp];
                ulonglong2 q0 = av[0], q1 = av[1], q2 = av[2], q3 = av[3];
                u64 a[8] = {q0.x, q0.y, q1.x, q1.y, q2.x, q2.y, q3.x, q3.y};
                #pragma unroll
                for (int pp = 0; pp < 8; pp++) {
                    acc[0][pp] = fma2(wp0, a[pp], acc[0][pp]);
                    acc[1][pp] = fma2(wp1, a[pp], acc[1][pp]);
                    acc[2][pp] = fma2(wp2, a[pp], acc[2][pp]);
                    acc[3][pp] = fma2(wp3, a[pp], acc[3][pp]);
                }
            }
            #pragma unroll
            for (int o = 0; o < 4; o++) {
                float4* row = (float4*)&s.A1[rowoff(4 * to + o) + 16 * tp];
                #pragma unroll
                for (int k = 0; k < 4; k++) {
                    float l0, h0, l1, h1;
                    unpack2(acc[o][2 * k + 0], l0, h0);
                    unpack2(acc[o][2 * k + 1], l1, h1);
                    row[k] = make_float4(fmaxf(l0, 0.0f), fmaxf(h0, 0.0f),
                                         fmaxf(l1, 0.0f), fmaxf(h1, 0.0f));
                }
            }
        }
        __syncthreads();

        // ---- phase 2: 64 -> 64 + relu, in-place on A1 ----
        {
            u64 acc[4][8];
            #pragma unroll
            for (int o = 0; o < 4; o++) {
                u64 bb = pack2(s.b2[4 * to + o]);
                #pragma unroll
                for (int pp = 0; pp < 8; pp++) acc[o][pp] = bb;
            }
            #pragma unroll 8
            for (int i = 0; i < HID; i++) {
                float4 w = *(const float4*)&s.w2[i * HID + 4 * to];
                u64 wp0 = pack2(w.x), wp1 = pack2(w.y), wp2 = pack2(w.z), wp3 = pack2(w.w);
                const ulonglong2* av = (const ulonglong2*)&s.A1[rowoff(i) + 16 * tp];
                ulonglong2 q0 = av[0], q1 = av[1], q2 = av[2], q3 = av[3];
                u64 a[8] = {q0.x, q0.y, q1.x, q1.y, q2.x, q2.y, q3.x, q3.y};
                #pragma unroll
                for (int pp = 0; pp < 8; pp++) {
                    acc[0][pp] = fma2(wp0, a[pp], acc[0][pp]);
                    acc[1][pp] = fma2(wp1, a[pp], acc[1][pp]);
                    acc[2][pp] = fma2(wp2, a[pp], acc[2][pp]);
                    acc[3][pp] = fma2(wp3, a[pp], acc[3][pp]);
                }
            }
            __syncthreads();   // all reads of A1 complete before overwrite
            #pragma unroll
            for (int o = 0; o < 4; o++) {
                float4* row = (float4*)&s.A1[rowoff(4 * to + o) + 16 * tp];
                #pragma unroll
                for (int k = 0; k < 4; k++) {
                    float l0, h0, l1, h1;
                    unpack2(acc[o][2 * k + 0], l0, h0);
                    unpack2(acc[o][2 * k + 1], l1, h1);
                    row[k] = make_float4(fmaxf(l0, 0.0f), fmaxf(h0, 0.0f),
                                         fmaxf(l1, 0.0f), fmaxf(h1, 0.0f));
                }
            }
        }
        __syncthreads();

        // ---- phase 3: 64 -> 3, one point per thread ----
        {
            u64 p01 = *(const u64*)&s.b3[0];
            u64 p23 = *(const u64*)&s.b3[2];
            const ulonglong2* w3v = (const ulonglong2*)s.w3;
            #pragma unroll 8
            for (int i = 0; i < HID; i++) {
                u64 ap = pack2(s.A1[rowoff(i) + tid]);
                ulonglong2 wq = w3v[i];
                p01 = fma2(ap, wq.x, p01);
                p23 = fma2(ap, wq.y, p23);
            }
            float o0, o1, o2, o3;
            unpack2(p01, o0, o1);
            unpack2(p23, o2, o3);
            int idx = base + tid;
            if (idx < n) {
                out[idx * 3 + 0] = o0;
                out[idx * 3 + 1] = o1;
                out[idx * 3 + 2] = o2;
            }
        }
        // next iteration's xs-write is fenced by the sync after xs staging
    }
}

extern "C" void kernel_launch(void* const* d_in, const int* in_sizes, int n_in,
                              void* d_out, int out_size) {
    const float* x    = (const float*)d_in[0];
    const float4* e0  = (const float4*)d_in[1];
    const float4* e1  = (const float4*)d_in[2];
    const float4* e2  = (const float4*)d_in[3];
    const float* w1   = (const float*)d_in[4];
    const float* b1   = (const float*)d_in[5];
    const float* w2   = (const float*)d_in[6];
    const float* b2   = (const float*)d_in[7];
    const float* w3   = (const float*)d_in[8];
    const float* b3   = (const float*)d_in[9];
    float* out        = (float*)d_out;
    int n = in_sizes[0] / 3;
    (void)n_in; (void)out_size;
    cudaFuncSetAttribute(densegrid_kernel,
                         cudaFuncAttributeMaxDynamicSharedMemorySize,
                         (int)sizeof(Smem));
    densegrid_kernel<<<BLOCKS, THREADS, sizeof(Smem)>>>(
        x, e0, e1, e2, w1, b1, w2, b2, w3, b3, out, n);
}